// round 14
// baseline (speedup 1.0000x reference)
#include <cuda_runtime.h>
#include <cuda_bf16.h>
#include <math.h>
#include <stdint.h>

// Problem constants
constexpr int Bc  = 2;
constexpr int Tc  = 2048;
constexpr int Dc  = 1024;
constexpr int Hc  = 16;
constexpr int HDc = 64;
constexpr int Mc  = Bc * Tc;      // 4096

// ---------------------------------------------------------------------------
// Scratch (device globals; no allocations allowed)
// ---------------------------------------------------------------------------
__device__ __nv_bfloat16 g_Xhi[Mc * Dc];             // k-pair-permuted
__device__ __nv_bfloat16 g_Xlo[Mc * Dc];
__device__ float         g_Q[Bc * Hc * Tc * HDc];    // raw f32
__device__ float         g_V[Bc * Hc * Tc * HDc];    // raw f32
__device__ __nv_bfloat16 g_Khi[Bc * Hc * Tc * HDc];  // d-pair-permuted
__device__ __nv_bfloat16 g_Klo[Bc * Hc * Tc * HDc];
__device__ __nv_bfloat16 g_Vthi[Bc * Hc * Tc * HDc]; // [bh][d][t], t-permuted
__device__ __nv_bfloat16 g_Vtlo[Bc * Hc * Tc * HDc];
__device__ __nv_bfloat16 g_Ahi[Mc * Dc];             // D-pair-permuted
__device__ __nv_bfloat16 g_Alo[Mc * Dc];
__device__ __nv_bfloat16 g_Wthi[4 * Dc * Dc];        // [n][k], k-permuted (q,k,v,o)
__device__ __nv_bfloat16 g_Wtlo[4 * Dc * Dc];

// ---------------------------------------------------------------------------
// Helpers
// ---------------------------------------------------------------------------
__device__ __host__ __forceinline__ int perm16(int c) {
    const int p = (c >> 1) & 7, e = c & 1;
    const int fp = ((p & 3) << 1) | (p >> 2);
    return (c & ~15) | (fp << 1) | e;
}

__device__ __forceinline__ uint32_t smem_to_u32(const void* p) {
    uint32_t a;
    asm("{ .reg .u64 t; cvta.to.shared.u64 t, %1; cvt.u32.u64 %0, t; }" : "=r"(a) : "l"(p));
    return a;
}

__device__ __forceinline__ void cp_async16(uint32_t saddr, const void* gaddr) {
    asm volatile("cp.async.cg.shared.global [%0], [%1], 16;" :: "r"(saddr), "l"(gaddr));
}
__device__ __forceinline__ void cp_commit() {
    asm volatile("cp.async.commit_group;" ::: "memory");
}
template <int N>
__device__ __forceinline__ void cp_wait() {
    asm volatile("cp.async.wait_group %0;" :: "n"(N) : "memory");
}

// bf16 m16n8k16 mma.sync (sm_80+)
__device__ __forceinline__ void mma_bf16(float* d, const uint32_t* a, const uint32_t* b) {
    asm volatile(
        "mma.sync.aligned.m16n8k16.row.col.f32.bf16.bf16.f32 "
        "{%0,%1,%2,%3}, {%4,%5,%6,%7}, {%8,%9}, {%0,%1,%2,%3};"
        : "+f"(d[0]), "+f"(d[1]), "+f"(d[2]), "+f"(d[3])
        : "r"(a[0]), "r"(a[1]), "r"(a[2]), "r"(a[3]), "r"(b[0]), "r"(b[1]));
}

__device__ __forceinline__ void split_bf16(float v, __nv_bfloat16& h, __nv_bfloat16& l) {
    h = __float2bfloat16_rn(v);
    l = __float2bfloat16_rn(v - __bfloat162float(h));
}
__device__ __forceinline__ uint32_t pack2(__nv_bfloat16 a, __nv_bfloat16 b) {
    __nv_bfloat162 t; t.x = a; t.y = b;
    return *(uint32_t*)&t;
}

// ---------------------------------------------------------------------------
// Prep: split X into bf16 hi/lo, k-pair-permuted
// ---------------------------------------------------------------------------
__global__ __launch_bounds__(256)
void split_permK_bf16(const float* __restrict__ in, __nv_bfloat16* __restrict__ hi,
                      __nv_bfloat16* __restrict__ lo, int n2)
{
    int i = blockIdx.x * 256 + threadIdx.x;
    if (i < n2) {
        const int j = 2 * i;
        const float2 v = *(const float2*)(in + j);
        const int p = (j >> 1) & 7;
        const int newj = (j & ~15) | ((((p & 3) << 1) | (p >> 2)) << 1);
        __nv_bfloat162 h, l;
        split_bf16(v.x, h.x, l.x);
        split_bf16(v.y, h.y, l.y);
        *(__nv_bfloat162*)(hi + newj) = h;
        *(__nv_bfloat162*)(lo + newj) = l;
    }
}

// ---------------------------------------------------------------------------
// Prep: per-head transpose+split of V: Vt[bh][d][perm16(t)] = split(V[bh][t][d])
// ---------------------------------------------------------------------------
__global__ __launch_bounds__(256)
void trans_split_V(const float* __restrict__ V, __nv_bfloat16* __restrict__ Thi,
                   __nv_bfloat16* __restrict__ Tlo)
{
    __shared__ float tile[32][33];
    const int bh = blockIdx.z;
    const int t0 = blockIdx.x * 32, d0 = blockIdx.y * 32;
    const int tx = threadIdx.x, ty = threadIdx.y;
    const float* src = V + (size_t)bh * Tc * HDc;
    #pragma unroll
    for (int j = 0; j < 32; j += 8)
        tile[ty + j][tx] = src[(size_t)(t0 + ty + j) * HDc + d0 + tx];
    __syncthreads();
    __nv_bfloat16* dh = Thi + (size_t)bh * HDc * Tc;
    __nv_bfloat16* dl = Tlo + (size_t)bh * HDc * Tc;
    const int txp = t0 + perm16(tx);
    #pragma unroll
    for (int j = 0; j < 32; j += 8) {
        __nv_bfloat16 h, l;
        split_bf16(tile[tx][ty + j], h, l);
        dh[(size_t)(d0 + ty + j) * Tc + txp] = h;
        dl[(size_t)(d0 + ty + j) * Tc + txp] = l;
    }
}

// ---------------------------------------------------------------------------
// Weight transpose + split + k-pair perm: Wt[n][perm16(k)] = split(W[k][n])
// ---------------------------------------------------------------------------
__global__ __launch_bounds__(256)
void transpose4_split(const float* __restrict__ W0, const float* __restrict__ W1,
                      const float* __restrict__ W2, const float* __restrict__ W3,
                      __nv_bfloat16* __restrict__ Thi, __nv_bfloat16* __restrict__ Tlo)
{
    __shared__ float tile[32][33];
    const int z = blockIdx.z;
    const float* W = (z == 0) ? W0 : (z == 1) ? W1 : (z == 2) ? W2 : W3;
    const size_t zoff = (size_t)z * Dc * Dc;

    const int tx = threadIdx.x, ty = threadIdx.y;
    int x = blockIdx.x * 32 + tx;
    int y = blockIdx.y * 32 + ty;
    #pragma unroll
    for (int j = 0; j < 32; j += 8)
        tile[ty + j][tx] = W[(size_t)(y + j) * Dc + x];
    __syncthreads();
    const int xp = blockIdx.y * 32 + perm16(tx);
    y = blockIdx.x * 32 + ty;
    #pragma unroll
    for (int j = 0; j < 32; j += 8) {
        __nv_bfloat16 h, l;
        split_bf16(tile[tx][ty + j], h, l);
        Thi[zoff + (size_t)(y + j) * Dc + xp] = h;
        Tlo[zoff + (size_t)(y + j) * Dc + xp] = l;
    }
}

// ---------------------------------------------------------------------------
// split-bf16 (3-term) GEMM core (R9 config: 128x128, BK=64, occ 1); FUSED QKV
// epilogue routes by column block. (R13-proven, unchanged)
// ---------------------------------------------------------------------------
constexpr int BM = 128, BN = 128, BKC2 = 64;
constexpr int NCH2 = Dc / BKC2;          // 16
constexpr int RSG = 80;                  // bf16 elements per smem row (160B)
constexpr int TILE_E = BM * RSG;         // 10240 elements
constexpr int STAGE_E = 4 * TILE_E;      // Ahi, Alo, Bhi, Blo
constexpr int GEMM_SMEM = 2 * STAGE_E * 2;   // 163840 B

template <bool FUSED>
__global__ __launch_bounds__(256, 1)
void gemm_bf16x3(const __nv_bfloat16* __restrict__ Xhi, const __nv_bfloat16* __restrict__ Xlo,
                 const __nv_bfloat16* __restrict__ Whi, const __nv_bfloat16* __restrict__ Wlo,
                 const float* __restrict__ b0p, const float* __restrict__ b1p,
                 const float* __restrict__ b2p,
                 float* __restrict__ Yq, __nv_bfloat16* __restrict__ Ykh,
                 __nv_bfloat16* __restrict__ Ykl, float* __restrict__ Yv)
{
    extern __shared__ __align__(16) char smem_raw[];
    __nv_bfloat16* smem_bf = (__nv_bfloat16*)smem_raw;
    const uint32_t sb = smem_to_u32(smem_raw);
    const int tid = threadIdx.x;
    const int wid = tid >> 5, lane = tid & 31;
    const int g = lane >> 2, tg = lane & 3;
    const int wm = wid & 1;
    const int wn = wid >> 1;
    const int m0 = blockIdx.y * BM;
    const int n0 = blockIdx.x * BN;

    auto load_chunk = [&](int k, int s) {
        const uint32_t sbase = sb + (uint32_t)s * STAGE_E * 2;
        const size_t aoff = (size_t)m0 * Dc + k * BKC2;
        const size_t boff = (size_t)n0 * Dc + k * BKC2;
        const __nv_bfloat16* srcs[4] = {Xhi + aoff, Xlo + aoff, Whi + boff, Wlo + boff};
        #pragma unroll
        for (int t = 0; t < 4; t++) {
            const __nv_bfloat16* gsrc = srcs[t];
            const uint32_t tbase = sbase + (uint32_t)t * TILE_E * 2;
            #pragma unroll
            for (int i = 0; i < 4; i++) {
                const int u = i * 256 + tid;
                const int row = u >> 3, c = u & 7;
                cp_async16(tbase + (uint32_t)(row * (RSG * 2) + c * 16),
                           gsrc + (size_t)row * Dc + c * 8);
            }
        }
        cp_commit();
    };

    float acc[4][4][4] = {};

    load_chunk(0, 0);
    load_chunk(1, 1);

    for (int k = 0; k < NCH2; k++) {
        const int s = k & 1;
        cp_wait<1>();
        __syncthreads();

        const __nv_bfloat16* As_hi = smem_bf + s * STAGE_E;
        const __nv_bfloat16* As_lo = As_hi + TILE_E;
        const __nv_bfloat16* Bs_hi = As_lo + TILE_E;
        const __nv_bfloat16* Bs_lo = Bs_hi + TILE_E;

        #pragma unroll
        for (int kk = 0; kk < 4; kk++) {
            const int eo = kk * 16 + 4 * tg;
            uint32_t ah[4][4], al[4][4], bh[4][2], bl[4][2];
            #pragma unroll
            for (int mi = 0; mi < 4; mi++) {
                const int r = (wm * 64 + mi * 16 + g) * RSG + eo;
                const uint2 h0 = *(const uint2*)(As_hi + r);
                const uint2 h1 = *(const uint2*)(As_hi + r + 8 * RSG);
                const uint2 l0 = *(const uint2*)(As_lo + r);
                const uint2 l1 = *(const uint2*)(As_lo + r + 8 * RSG);
                ah[mi][0] = h0.x; ah[mi][1] = h1.x; ah[mi][2] = h0.y; ah[mi][3] = h1.y;
                al[mi][0] = l0.x; al[mi][1] = l1.x; al[mi][2] = l0.y; al[mi][3] = l1.y;
            }
            #pragma unroll
            for (int ni = 0; ni < 4; ni++) {
                const int r = (wn * 32 + ni * 8 + g) * RSG + eo;
                const uint2 hb = *(const uint2*)(Bs_hi + r);
                const uint2 lb = *(const uint2*)(Bs_lo + r);
                bh[ni][0] = hb.x; bh[ni][1] = hb.y;
                bl[ni][0] = lb.x; bl[ni][1] = lb.y;
            }
            #pragma unroll
            for (int mi = 0; mi < 4; mi++)
                #pragma unroll
                for (int ni = 0; ni < 4; ni++) {
                    mma_bf16(acc[mi][ni], al[mi], bh[ni]);
                    mma_bf16(acc[mi][ni], ah[mi], bl[ni]);
                    mma_bf16(acc[mi][ni], ah[mi], bh[ni]);
                }
        }

        __syncthreads();
        if (k + 2 < NCH2) load_chunk(k + 2, s); else cp_commit();
    }

    const int mat = FUSED ? (n0 >> 10) : 0;
    const float* bias = FUSED ? ((mat == 0) ? b0p : (mat == 1) ? b1p : b2p) : b0p;

    #pragma unroll
    for (int mi = 0; mi < 4; mi++) {
        const int row0 = m0 + wm * 64 + mi * 16 + g;
        #pragma unroll
        for (int ni = 0; ni < 4; ni++) {
            const int gcol = n0 + wn * 32 + ni * 8 + 2 * tg;
            const int col = gcol & 1023;
            const float2 bv = *(const float2*)&bias[col];
            float2 v0, v1;
            v0.x = acc[mi][ni][0] + bv.x;  v0.y = acc[mi][ni][1] + bv.y;
            v1.x = acc[mi][ni][2] + bv.x;  v1.y = acc[mi][ni][3] + bv.y;
            if (!FUSED) {
                *(float2*)(Yq + (size_t)row0 * Dc + col) = v0;
                *(float2*)(Yq + (size_t)(row0 + 8) * Dc + col) = v1;
            } else {
                const int h = col >> 6, d0 = col & 63;
                const int b0i = row0 >> 11, t0 = row0 & 2047;
                const size_t q0 = (((size_t)b0i * Hc + h) * Tc + t0) << 6;
                const int row1 = row0 + 8;
                const int b1i = row1 >> 11, t1 = row1 & 2047;
                const size_t q1 = (((size_t)b1i * Hc + h) * Tc + t1) << 6;
                if (mat == 0) {
                    *(float2*)(Yq + q0 + d0) = v0;
                    *(float2*)(Yq + q1 + d0) = v1;
                } else if (mat == 2) {
                    *(float2*)(Yv + q0 + d0) = v0;
                    *(float2*)(Yv + q1 + d0) = v1;
                } else {
                    const int dp0 = perm16(d0);
                    __nv_bfloat162 hh, ll;
                    split_bf16(v0.x, hh.x, ll.x);
                    split_bf16(v0.y, hh.y, ll.y);
                    *(__nv_bfloat162*)(Ykh + q0 + dp0) = hh;
                    *(__nv_bfloat162*)(Ykl + q0 + dp0) = ll;
                    split_bf16(v1.x, hh.x, ll.x);
                    split_bf16(v1.y, hh.y, ll.y);
                    *(__nv_bfloat162*)(Ykh + q1 + dp0) = hh;
                    *(__nv_bfloat162*)(Ykl + q1 + dp0) = ll;
                }
            }
        }
    }
}

// ---------------------------------------------------------------------------
// split-bf16 flash attention, causal. AQ=64, AKT=64, 4 warps, P in registers.
// K double-buffered, V SINGLE-buffered -> 60KB smem -> 3 CTAs/SM.
// Pipeline groups per iter: [V(t+1)] then [K(t+2)] (empty commits at bounds).
// ---------------------------------------------------------------------------
constexpr int AQ  = 64;
constexpr int AKT = 64;
constexpr int RSK = 80;
constexpr int RSV = 80;
constexpr int KT_E = AKT * RSK;          // 5120 (per hi or lo)
constexpr int VT_E = HDc * RSV;          // 5120
// layout: K0hi | K0lo | K1hi | K1lo | Vhi | Vlo
constexpr int OFF_V = 4 * KT_E;          // 20480
constexpr int ATTN_SMEM = (4 * KT_E + 2 * VT_E) * 2;   // 61440 B

__global__ __launch_bounds__(128, 3)
void attn_bf16(const float* __restrict__ Q,
               const __nv_bfloat16* __restrict__ Khi, const __nv_bfloat16* __restrict__ Klo,
               const __nv_bfloat16* __restrict__ Vthi, const __nv_bfloat16* __restrict__ Vtlo,
               __nv_bfloat16* __restrict__ Ohi, __nv_bfloat16* __restrict__ Olo)
{
    extern __shared__ __align__(16) char asmem[];
    __nv_bfloat16* smem_bf = (__nv_bfloat16*)asmem;
    const uint32_t sb = smem_to_u32(asmem);
    const int tid = threadIdx.x, wid = tid >> 5, lane = tid & 31;
    const int g = lane >> 2, tg = lane & 3;
    const int bh = blockIdx.y;
    const int q0 = (int)(gridDim.x - 1 - blockIdx.x) * AQ;
    const int b = bh >> 4, h = bh & 15;
    const int nt = q0 / AKT + 1;

    uint32_t qhi[4][4], qlo[4][4];
    {
        const float* qb = Q + ((size_t)bh * Tc + q0 + wid * 16) * HDc;
        #pragma unroll
        for (int kk = 0; kk < 4; kk++) {
            const int ks = kk * 16 + 2 * tg;
            const float2 v00 = *(const float2*)&qb[(size_t)g * HDc + ks];
            const float2 v01 = *(const float2*)&qb[(size_t)g * HDc + ks + 8];
            const float2 v10 = *(const float2*)&qb[(size_t)(g + 8) * HDc + ks];
            const float2 v11 = *(const float2*)&qb[(size_t)(g + 8) * HDc + ks + 8];
            __nv_bfloat16 hx, lx, hy, ly;
            split_bf16(v00.x * 0.125f, hx, lx); split_bf16(v00.y * 0.125f, hy, ly);
            qhi[kk][0] = pack2(hx, hy); qlo[kk][0] = pack2(lx, ly);
            split_bf16(v10.x * 0.125f, hx, lx); split_bf16(v10.y * 0.125f, hy, ly);
            qhi[kk][1] = pack2(hx, hy); qlo[kk][1] = pack2(lx, ly);
            split_bf16(v01.x * 0.125f, hx, lx); split_bf16(v01.y * 0.125f, hy, ly);
            qhi[kk][2] = pack2(hx, hy); qlo[kk][2] = pack2(lx, ly);
            split_bf16(v11.x * 0.125f, hx, lx); split_bf16(v11.y * 0.125f, hy, ly);
            qhi[kk][3] = pack2(hx, hy); qlo[kk][3] = pack2(lx, ly);
        }
    }

    auto load_K = [&](int t_, int s_) {
        const uint32_t base = sb + (uint32_t)(s_ * 2 * KT_E) * 2;
        const size_t kg = ((size_t)bh * Tc + t_ * AKT) * HDc;
        #pragma unroll
        for (int i = 0; i < 4; i++) {
            const int u = i * 128 + tid;
            const int r = u >> 3, c = u & 7;
            cp_async16(base + (uint32_t)(r * RSK + c * 8) * 2, Khi + kg + (size_t)r * HDc + c * 8);
        }
        #pragma unroll
        for (int i = 0; i < 4; i++) {
            const int u = i * 128 + tid;
            const int r = u >> 3, c = u & 7;
            cp_async16(base + (uint32_t)(KT_E + r * RSK + c * 8) * 2, Klo + kg + (size_t)r * HDc + c * 8);
        }
    };
    auto load_V = [&](int t_) {
        const uint32_t base = sb + (uint32_t)OFF_V * 2;
        const size_t vg = (size_t)bh * HDc * Tc + t_ * AKT;
        #pragma unroll
        for (int i = 0; i < 4; i++) {
            const int u = i * 128 + tid;
            const int r = u >> 3, c = u & 7;
            cp_async16(base + (uint32_t)(r * RSV + c * 8) * 2, Vthi + vg + (size_t)r * Tc + c * 8);
        }
        #pragma unroll
        for (int i = 0; i < 4; i++) {
            const int u = i * 128 + tid;
            const int r = u >> 3, c = u & 7;
            cp_async16(base + (uint32_t)(VT_E + r * RSV + c * 8) * 2, Vtlo + vg + (size_t)r * Tc + c * 8);
        }
    };

    float acc_o[8][4] = {};
    float m0 = -INFINITY, m1 = -INFINITY, l0 = 0.f, l1 = 0.f;
    const int row0 = q0 + wid * 16 + g;

    // prologue: 3 groups [K0][V0][K1]
    load_K(0, 0); cp_commit();
    load_V(0);    cp_commit();
    if (nt > 1) load_K(1, 1);
    cp_commit();

    for (int t = 0; t < nt; t++) {
        const int k0 = t * AKT;
        cp_wait<2>();            // K(t) ready; V(t), K(t+1) may be in flight
        __syncthreads();

        const __nv_bfloat16* Ks_hi = smem_bf + (t & 1) * 2 * KT_E;
        const __nv_bfloat16* Ks_lo = Ks_hi + KT_E;
        const __nv_bfloat16* Vs_hi = smem_bf + OFF_V;
        const __nv_bfloat16* Vs_lo = Vs_hi + VT_E;

        float sacc[8][4] = {};
        #pragma unroll
        for (int kk = 0; kk < 4; kk++) {
            #pragma unroll
            for (int n_ = 0; n_ < 8; n_++) {
                const int r = (n_ * 8 + g) * RSK + kk * 16 + 4 * tg;
                const uint2 kh2 = *(const uint2*)(Ks_hi + r);
                const uint2 kl2 = *(const uint2*)(Ks_lo + r);
                uint32_t kh[2] = {kh2.x, kh2.y};
                uint32_t kl[2] = {kl2.x, kl2.y};
                mma_bf16(sacc[n_], qlo[kk], kh);
                mma_bf16(sacc[n_], qhi[kk], kl);
                mma_bf16(sacc[n_], qhi[kk], kh);
            }
        }

        if (k0 + AKT - 1 > q0 + wid * 16) {
            #pragma unroll
            for (int n_ = 0; n_ < 8; n_++) {
                const int c0 = k0 + n_ * 8 + 2 * tg;
                if (c0 > row0)     sacc[n_][0] = -1e30f;
                if (c0 + 1 > row0) sacc[n_][1] = -1e30f;
                if (c0 > row0 + 8)     sacc[n_][2] = -1e30f;
                if (c0 + 1 > row0 + 8) sacc[n_][3] = -1e30f;
            }
        }

        float tx0 = sacc[0][0], tx1 = sacc[0][2];
        #pragma unroll
        for (int n_ = 0; n_ < 8; n_++) {
            tx0 = fmaxf(tx0, fmaxf(sacc[n_][0], sacc[n_][1]));
            tx1 = fmaxf(tx1, fmaxf(sacc[n_][2], sacc[n_][3]));
        }
        tx0 = fmaxf(tx0, __shfl_xor_sync(0xffffffffu, tx0, 1));
        tx0 = fmaxf(tx0, __shfl_xor_sync(0xffffffffu, tx0, 2));
        tx1 = fmaxf(tx1, __shfl_xor_sync(0xffffffffu, tx1, 1));
        tx1 = fmaxf(tx1, __shfl_xor_sync(0xffffffffu, tx1, 2));
        const float mn0 = fmaxf(m0, tx0), mn1 = fmaxf(m1, tx1);
        const float c0f = __expf(m0 - mn0), c1f = __expf(m1 - mn1);
        m0 = mn0; m1 = mn1;

        float rs0 = 0.f, rs1 = 0.f;
        #pragma unroll
        for (int n_ = 0; n_ < 8; n_++) {
            sacc[n_][0] = __expf(sacc[n_][0] - mn0);
            sacc[n_][1] = __expf(sacc[n_][1] - mn0);
            sacc[n_][2] = __expf(sacc[n_][2] - mn1);
            sacc[n_][3] = __expf(sacc[n_][3] - mn1);
            rs0 += sacc[n_][0] + sacc[n_][1];
            rs1 += sacc[n_][2] + sacc[n_][3];
        }
        rs0 += __shfl_xor_sync(0xffffffffu, rs0, 1);
        rs0 += __shfl_xor_sync(0xffffffffu, rs0, 2);
        rs1 += __shfl_xor_sync(0xffffffffu, rs1, 1);
        rs1 += __shfl_xor_sync(0xffffffffu, rs1, 2);
        l0 = l0 * c0f + rs0;
        l1 = l1 * c1f + rs1;

        #pragma unroll
        for (int d8 = 0; d8 < 8; d8++) {
            acc_o[d8][0] *= c0f; acc_o[d8][1] *= c0f;
            acc_o[d8][2] *= c1f; acc_o[d8][3] *= c1f;
        }

        cp_wait<1>();            // V(t) ready; K(t+1) may still be in flight
        __syncthreads();

        #pragma unroll
        for (int kk = 0; kk < 4; kk++) {
            uint32_t pah[4], pal[4];
            __nv_bfloat16 h0, l0b, h1, l1b;
            split_bf16(sacc[2*kk][0], h0, l0b); split_bf16(sacc[2*kk][1], h1, l1b);
            pah[0] = pack2(h0, h1); pal[0] = pack2(l0b, l1b);
            split_bf16(sacc[2*kk][2], h0, l0b); split_bf16(sacc[2*kk][3], h1, l1b);
            pah[1] = pack2(h0, h1); pal[1] = pack2(l0b, l1b);
            split_bf16(sacc[2*kk+1][0], h0, l0b); split_bf16(sacc[2*kk+1][1], h1, l1b);
            pah[2] = pack2(h0, h1); pal[2] = pack2(l0b, l1b);
            split_bf16(sacc[2*kk+1][2], h0, l0b); split_bf16(sacc[2*kk+1][3], h1, l1b);
            pah[3] = pack2(h0, h1); pal[3] = pack2(l0b, l1b);
            #pragma unroll
            for (int d8 = 0; d8 < 8; d8++) {
                const int r = (d8 * 8 + g) * RSV + kk * 16 + 4 * tg;
                const uint2 vh2 = *(const uint2*)(Vs_hi + r);
                const uint2 vl2 = *(const uint2*)(Vs_lo + r);
                uint32_t vh[2] = {vh2.x, vh2.y};
                uint32_t vl[2] = {vl2.x, vl2.y};
                mma_bf16(acc_o[d8], pal, vh);
                mma_bf16(acc_o[d8], pah, vl);
                mma_bf16(acc_o[d8], pah, vh);
            }
        }

        __syncthreads();         // V buffer + K(t) buffer free

        if (t + 1 < nt) load_V(t + 1);
        cp_commit();             // group [V(t+1)] (possibly empty)
        if (t + 2 < nt) load_K(t + 2, t & 1);
        cp_commit();             // group [K(t+2)] (possibly empty)
    }

    const float il0 = 1.f / l0, il1 = 1.f / l1;
    const size_t ob0 = ((size_t)b * Tc + row0) * Dc + (size_t)h * HDc;
    const size_t ob1 = ob0 + (size_t)8 * Dc;
    #pragma unroll
    for (int d8 = 0; d8 < 8; d8++) {
        const int c = d8 * 8 + 2 * tg;
        const int cp0 = perm16(c);
        const float v0 = acc_o[d8][0] * il0, v1 = acc_o[d8][1] * il0;
        const float v2 = acc_o[d8][2] * il1, v3 = acc_o[d8][3] * il1;
        __nv_bfloat162 hh, ll;
        split_bf16(v0, hh.x, ll.x); split_bf16(v1, hh.y, ll.y);
        *(__nv_bfloat162*)(Ohi + ob0 + cp0) = hh;
        *(__nv_bfloat162*)(Olo + ob0 + cp0) = ll;
        split_bf16(v2, hh.x, ll.x); split_bf16(v3, hh.y, ll.y);
        *(__nv_bfloat162*)(Ohi + ob1 + cp0) = hh;
        *(__nv_bfloat162*)(Olo + ob1 + cp0) = ll;
    }
}

// ---------------------------------------------------------------------------
// Launch
// ---------------------------------------------------------------------------
extern "C" void kernel_launch(void* const* d_in, const int* in_sizes, int n_in,
                              void* d_out, int out_size)
{
    const float* x  = (const float*)d_in[0];
    const float* Wq = (const float*)d_in[1];
    const float* bq = (const float*)d_in[2];
    const float* Wk = (const float*)d_in[3];
    const float* bk = (const float*)d_in[4];
    const float* Wv = (const float*)d_in[5];
    const float* bv = (const float*)d_in[6];
    const float* Wo = (const float*)d_in[7];
    const float* bo = (const float*)d_in[8];
    float* out = (float*)d_out;

    __nv_bfloat16 *Xhi, *Xlo, *Khi, *Klo, *Vthi, *Vtlo, *Ahi, *Alo, *Whi, *Wlo;
    float *Qp, *Vp;
    cudaGetSymbolAddress((void**)&Xhi, g_Xhi);
    cudaGetSymbolAddress((void**)&Xlo, g_Xlo);
    cudaGetSymbolAddress((void**)&Qp, g_Q);
    cudaGetSymbolAddress((void**)&Vp, g_V);
    cudaGetSymbolAddress((void**)&Khi, g_Khi);
    cudaGetSymbolAddress((void**)&Klo, g_Klo);
    cudaGetSymbolAddress((void**)&Vthi, g_Vthi);
    cudaGetSymbolAddress((void**)&Vtlo, g_Vtlo);
    cudaGetSymbolAddress((void**)&Ahi, g_Ahi);
    cudaGetSymbolAddress((void**)&Alo, g_Alo);
    cudaGetSymbolAddress((void**)&Whi, g_Wthi);
    cudaGetSymbolAddress((void**)&Wlo, g_Wtlo);

    cudaFuncSetAttribute(gemm_bf16x3<false>, cudaFuncAttributeMaxDynamicSharedMemorySize, GEMM_SMEM);
    cudaFuncSetAttribute(gemm_bf16x3<true>,  cudaFuncAttributeMaxDynamicSharedMemorySize, GEMM_SMEM);
    cudaFuncSetAttribute(attn_bf16, cudaFuncAttributeMaxDynamicSharedMemorySize, ATTN_SMEM);

    // 1) prep: split+permute X; transpose+split+permute weights
    const int n2 = Mc * Dc / 2;
    split_permK_bf16<<<(n2 + 255) / 256, 256>>>(x, Xhi, Xlo, n2);
    transpose4_split<<<dim3(32, 32, 4), dim3(32, 8)>>>(Wq, Wk, Wv, Wo, Whi, Wlo);

    // 2) fused Q+K+V projection (one GEMM over N=3072)
    const dim3 gqkv(3 * Dc / BN, Mc / BM);   // (24, 32)
    gemm_bf16x3<true><<<gqkv, 256, GEMM_SMEM>>>(Xhi, Xlo, Whi, Wlo,
                                                bq, bk, bv, Qp, Khi, Klo, Vp);

    // 3) prep V (transpose + split + t-permute)
    trans_split_V<<<dim3(Tc / 32, HDc / 32, Bc * Hc), dim3(32, 8)>>>(Vp, Vthi, Vtlo);

    // 4) attention (occ 3: single-buffered V)
    const dim3 ag(Tc / AQ, Bc * Hc);   // (32, 32)
    attn_bf16<<<ag, 128, ATTN_SMEM>>>(Qp, Khi, Klo, Vthi, Vtlo, Ahi, Alo);

    // 5) output projection -> d_out
    const dim3 go(Dc / BN, Mc / BM);   // (8, 32)
    const size_t DD = (size_t)Dc * Dc;
    gemm_bf16x3<false><<<go, 256, GEMM_SMEM>>>(Ahi, Alo, Whi + 3 * DD, Wlo + 3 * DD,
                                               bo, nullptr, nullptr, out, nullptr, nullptr, nullptr);
}

// round 17
// speedup vs baseline: 1.0203x; 1.0203x over previous
#include <cuda_runtime.h>
#include <cuda_bf16.h>
#include <math.h>
#include <stdint.h>

// Problem constants
constexpr int Bc  = 2;
constexpr int Tc  = 2048;
constexpr int Dc  = 1024;
constexpr int Hc  = 16;
constexpr int HDc = 64;
constexpr int Mc  = Bc * Tc;      // 4096

// ---------------------------------------------------------------------------
// Scratch (device globals; no allocations allowed)
// ---------------------------------------------------------------------------
__device__ __nv_bfloat16 g_Xhi[Mc * Dc];             // k-pair-permuted
__device__ __nv_bfloat16 g_Xlo[Mc * Dc];
__device__ float         g_Q[Bc * Hc * Tc * HDc];    // raw f32
__device__ __nv_bfloat16 g_Khi[Bc * Hc * Tc * HDc];  // d-pair-permuted
__device__ __nv_bfloat16 g_Klo[Bc * Hc * Tc * HDc];
__device__ __nv_bfloat16 g_Vthi[Bc * Hc * Tc * HDc]; // [bh][d][t], t-permuted
__device__ __nv_bfloat16 g_Vtlo[Bc * Hc * Tc * HDc];
__device__ __nv_bfloat16 g_Ahi[Mc * Dc];             // D-pair-permuted
__device__ __nv_bfloat16 g_Alo[Mc * Dc];
__device__ __nv_bfloat16 g_Wthi[4 * Dc * Dc];        // [n][k], k-permuted (q,k,v,o)
__device__ __nv_bfloat16 g_Wtlo[4 * Dc * Dc];

// ---------------------------------------------------------------------------
// Helpers
// ---------------------------------------------------------------------------
__device__ __host__ __forceinline__ int perm16(int c) {
    const int p = (c >> 1) & 7, e = c & 1;
    const int fp = ((p & 3) << 1) | (p >> 2);
    return (c & ~15) | (fp << 1) | e;
}

__device__ __forceinline__ uint32_t smem_to_u32(const void* p) {
    uint32_t a;
    asm("{ .reg .u64 t; cvta.to.shared.u64 t, %1; cvt.u32.u64 %0, t; }" : "=r"(a) : "l"(p));
    return a;
}

__device__ __forceinline__ void cp_async16(uint32_t saddr, const void* gaddr) {
    asm volatile("cp.async.cg.shared.global [%0], [%1], 16;" :: "r"(saddr), "l"(gaddr));
}
__device__ __forceinline__ void cp_commit() {
    asm volatile("cp.async.commit_group;" ::: "memory");
}
template <int N>
__device__ __forceinline__ void cp_wait() {
    asm volatile("cp.async.wait_group %0;" :: "n"(N) : "memory");
}

// bf16 m16n8k16 mma.sync (sm_80+)
__device__ __forceinline__ void mma_bf16(float* d, const uint32_t* a, const uint32_t* b) {
    asm volatile(
        "mma.sync.aligned.m16n8k16.row.col.f32.bf16.bf16.f32 "
        "{%0,%1,%2,%3}, {%4,%5,%6,%7}, {%8,%9}, {%0,%1,%2,%3};"
        : "+f"(d[0]), "+f"(d[1]), "+f"(d[2]), "+f"(d[3])
        : "r"(a[0]), "r"(a[1]), "r"(a[2]), "r"(a[3]), "r"(b[0]), "r"(b[1]));
}

__device__ __forceinline__ void split_bf16(float v, __nv_bfloat16& h, __nv_bfloat16& l) {
    h = __float2bfloat16_rn(v);
    l = __float2bfloat16_rn(v - __bfloat162float(h));
}
__device__ __forceinline__ uint32_t pack2(__nv_bfloat16 a, __nv_bfloat16 b) {
    __nv_bfloat162 t; t.x = a; t.y = b;
    return *(uint32_t*)&t;
}

// ---------------------------------------------------------------------------
// Prep: split X into bf16 hi/lo, k-pair-permuted
// ---------------------------------------------------------------------------
__global__ __launch_bounds__(256)
void split_permK_bf16(const float* __restrict__ in, __nv_bfloat16* __restrict__ hi,
                      __nv_bfloat16* __restrict__ lo, int n2)
{
    int i = blockIdx.x * 256 + threadIdx.x;
    if (i < n2) {
        const int j = 2 * i;
        const float2 v = *(const float2*)(in + j);
        const int p = (j >> 1) & 7;
        const int newj = (j & ~15) | ((((p & 3) << 1) | (p >> 2)) << 1);
        __nv_bfloat162 h, l;
        split_bf16(v.x, h.x, l.x);
        split_bf16(v.y, h.y, l.y);
        *(__nv_bfloat162*)(hi + newj) = h;
        *(__nv_bfloat162*)(lo + newj) = l;
    }
}

// ---------------------------------------------------------------------------
// Weight transpose + split + k-pair perm: Wt[n][perm16(k)] = split(W[k][n])
// ---------------------------------------------------------------------------
__global__ __launch_bounds__(256)
void transpose4_split(const float* __restrict__ W0, const float* __restrict__ W1,
                      const float* __restrict__ W2, const float* __restrict__ W3,
                      __nv_bfloat16* __restrict__ Thi, __nv_bfloat16* __restrict__ Tlo)
{
    __shared__ float tile[32][33];
    const int z = blockIdx.z;
    const float* W = (z == 0) ? W0 : (z == 1) ? W1 : (z == 2) ? W2 : W3;
    const size_t zoff = (size_t)z * Dc * Dc;

    const int tx = threadIdx.x, ty = threadIdx.y;
    int x = blockIdx.x * 32 + tx;
    int y = blockIdx.y * 32 + ty;
    #pragma unroll
    for (int j = 0; j < 32; j += 8)
        tile[ty + j][tx] = W[(size_t)(y + j) * Dc + x];
    __syncthreads();
    const int xp = blockIdx.y * 32 + perm16(tx);
    y = blockIdx.x * 32 + ty;
    #pragma unroll
    for (int j = 0; j < 32; j += 8) {
        __nv_bfloat16 h, l;
        split_bf16(tile[tx][ty + j], h, l);
        Thi[zoff + (size_t)(y + j) * Dc + xp] = h;
        Tlo[zoff + (size_t)(y + j) * Dc + xp] = l;
    }
}

// ---------------------------------------------------------------------------
// split-bf16 (3-term) GEMM core (128x128, BK=64, occ 1); FUSED QKV epilogue:
//   mat 0 (Q): f32 head-split; mat 1 (K): bf16 hi/lo d-permuted;
//   mat 2 (V): TRANSPOSED bf16 hi/lo -> Vt[bh][d][perm16(t)] via smem staging.
// ---------------------------------------------------------------------------
constexpr int BM = 128, BN = 128, BKC2 = 64;
constexpr int NCH2 = Dc / BKC2;          // 16
constexpr int RSG = 80;                  // bf16 elements per smem row (160B)
constexpr int TILE_E = BM * RSG;         // 10240 elements
constexpr int STAGE_E = 4 * TILE_E;      // Ahi, Alo, Bhi, Blo
constexpr int GEMM_SMEM = 2 * STAGE_E * 2;   // 163840 B
constexpr int VST = 129;                 // V staging row stride (floats)

template <bool FUSED>
__global__ __launch_bounds__(256, 1)
void gemm_bf16x3(const __nv_bfloat16* __restrict__ Xhi, const __nv_bfloat16* __restrict__ Xlo,
                 const __nv_bfloat16* __restrict__ Whi, const __nv_bfloat16* __restrict__ Wlo,
                 const float* __restrict__ b0p, const float* __restrict__ b1p,
                 const float* __restrict__ b2p,
                 float* __restrict__ Yq, __nv_bfloat16* __restrict__ Ykh,
                 __nv_bfloat16* __restrict__ Ykl,
                 __nv_bfloat16* __restrict__ Yvh, __nv_bfloat16* __restrict__ Yvl)
{
    extern __shared__ __align__(16) char smem_raw[];
    __nv_bfloat16* smem_bf = (__nv_bfloat16*)smem_raw;
    const uint32_t sb = smem_to_u32(smem_raw);
    const int tid = threadIdx.x;
    const int wid = tid >> 5, lane = tid & 31;
    const int g = lane >> 2, tg = lane & 3;
    const int wm = wid & 1;
    const int wn = wid >> 1;
    const int m0 = blockIdx.y * BM;
    const int n0 = blockIdx.x * BN;

    auto load_chunk = [&](int k, int s) {
        const uint32_t sbase = sb + (uint32_t)s * STAGE_E * 2;
        const size_t aoff = (size_t)m0 * Dc + k * BKC2;
        const size_t boff = (size_t)n0 * Dc + k * BKC2;
        const __nv_bfloat16* srcs[4] = {Xhi + aoff, Xlo + aoff, Whi + boff, Wlo + boff};
        #pragma unroll
        for (int t = 0; t < 4; t++) {
            const __nv_bfloat16* gsrc = srcs[t];
            const uint32_t tbase = sbase + (uint32_t)t * TILE_E * 2;
            #pragma unroll
            for (int i = 0; i < 4; i++) {
                const int u = i * 256 + tid;
                const int row = u >> 3, c = u & 7;
                cp_async16(tbase + (uint32_t)(row * (RSG * 2) + c * 16),
                           gsrc + (size_t)row * Dc + c * 8);
            }
        }
        cp_commit();
    };

    float acc[4][4][4] = {};

    load_chunk(0, 0);
    load_chunk(1, 1);

    for (int k = 0; k < NCH2; k++) {
        const int s = k & 1;
        cp_wait<1>();
        __syncthreads();

        const __nv_bfloat16* As_hi = smem_bf + s * STAGE_E;
        const __nv_bfloat16* As_lo = As_hi + TILE_E;
        const __nv_bfloat16* Bs_hi = As_lo + TILE_E;
        const __nv_bfloat16* Bs_lo = Bs_hi + TILE_E;

        #pragma unroll
        for (int kk = 0; kk < 4; kk++) {
            const int eo = kk * 16 + 4 * tg;
            uint32_t ah[4][4], al[4][4], bh[4][2], bl[4][2];
            #pragma unroll
            for (int mi = 0; mi < 4; mi++) {
                const int r = (wm * 64 + mi * 16 + g) * RSG + eo;
                const uint2 h0 = *(const uint2*)(As_hi + r);
                const uint2 h1 = *(const uint2*)(As_hi + r + 8 * RSG);
                const uint2 l0 = *(const uint2*)(As_lo + r);
                const uint2 l1 = *(const uint2*)(As_lo + r + 8 * RSG);
                ah[mi][0] = h0.x; ah[mi][1] = h1.x; ah[mi][2] = h0.y; ah[mi][3] = h1.y;
                al[mi][0] = l0.x; al[mi][1] = l1.x; al[mi][2] = l0.y; al[mi][3] = l1.y;
            }
            #pragma unroll
            for (int ni = 0; ni < 4; ni++) {
                const int r = (wn * 32 + ni * 8 + g) * RSG + eo;
                const uint2 hb = *(const uint2*)(Bs_hi + r);
                const uint2 lb = *(const uint2*)(Bs_lo + r);
                bh[ni][0] = hb.x; bh[ni][1] = hb.y;
                bl[ni][0] = lb.x; bl[ni][1] = lb.y;
            }
            #pragma unroll
            for (int mi = 0; mi < 4; mi++)
                #pragma unroll
                for (int ni = 0; ni < 4; ni++) {
                    mma_bf16(acc[mi][ni], al[mi], bh[ni]);
                    mma_bf16(acc[mi][ni], ah[mi], bl[ni]);
                    mma_bf16(acc[mi][ni], ah[mi], bh[ni]);
                }
        }

        __syncthreads();
        if (k + 2 < NCH2) load_chunk(k + 2, s); else cp_commit();
    }

    const int mat = FUSED ? (n0 >> 10) : 0;
    const float* bias = FUSED ? ((mat == 0) ? b0p : (mat == 1) ? b1p : b2p) : b0p;
    const int nb = n0 & 1023;             // within-matrix column base of this CTA

    if (FUSED && mat == 2) {
        // ---- V: stage biased f32 tile in smem, then transposed split write ----
        float* vst = (float*)smem_raw;    // [128][VST] = 66048 B
        #pragma unroll
        for (int mi = 0; mi < 4; mi++) {
            const int rl0 = wm * 64 + mi * 16 + g;
            #pragma unroll
            for (int ni = 0; ni < 4; ni++) {
                const int cl = wn * 32 + ni * 8 + 2 * tg;
                const float2 bv = *(const float2*)&bias[nb + cl];   // FIX: + nb
                vst[rl0 * VST + cl]           = acc[mi][ni][0] + bv.x;
                vst[rl0 * VST + cl + 1]       = acc[mi][ni][1] + bv.y;
                vst[(rl0 + 8) * VST + cl]     = acc[mi][ni][2] + bv.x;
                vst[(rl0 + 8) * VST + cl + 1] = acc[mi][ni][3] + bv.y;
            }
        }
        __syncthreads();
        const int b0i = m0 >> 11;
        const int tbase = m0 & 2047;
        #pragma unroll
        for (int it = 0; it < 32; it++) {
            const int u = it * 256 + tid;    // 0..8191: 128 cols x 64 t-pairs
            const int tp = u & 63;           // t-pair index (lanes along t -> coalesced STG)
            const int c  = u >> 6;           // local col 0..127
            const float x0 = vst[(2 * tp) * VST + c];
            const float x1 = vst[(2 * tp + 1) * VST + c];
            __nv_bfloat162 hh, ll;
            split_bf16(x0, hh.x, ll.x);
            split_bf16(x1, hh.y, ll.y);
            const int ncol = nb + c;                       // FIX: global V column
            const int h = ncol >> 6, d = ncol & 63;
            const int tl = 2 * tp;
            const int p = (tl >> 1) & 7;
            const int fp = ((p & 3) << 1) | (p >> 2);
            const int tpos = ((tbase + tl) & ~15) | (fp << 1);
            const size_t dst = (((size_t)b0i * Hc + h) * HDc + d) * Tc + tpos;
            *(__nv_bfloat162*)(Yvh + dst) = hh;
            *(__nv_bfloat162*)(Yvl + dst) = ll;
        }
        return;
    }

    #pragma unroll
    for (int mi = 0; mi < 4; mi++) {
        const int row0 = m0 + wm * 64 + mi * 16 + g;
        #pragma unroll
        for (int ni = 0; ni < 4; ni++) {
            const int gcol = n0 + wn * 32 + ni * 8 + 2 * tg;
            const int col = gcol & 1023;
            const float2 bv = *(const float2*)&bias[col];
            float2 v0, v1;
            v0.x = acc[mi][ni][0] + bv.x;  v0.y = acc[mi][ni][1] + bv.y;
            v1.x = acc[mi][ni][2] + bv.x;  v1.y = acc[mi][ni][3] + bv.y;
            if (!FUSED) {
                *(float2*)(Yq + (size_t)row0 * Dc + col) = v0;
                *(float2*)(Yq + (size_t)(row0 + 8) * Dc + col) = v1;
            } else {
                const int h = col >> 6, d0 = col & 63;
                const int b0i = row0 >> 11, t0 = row0 & 2047;
                const size_t q0 = (((size_t)b0i * Hc + h) * Tc + t0) << 6;
                const int row1 = row0 + 8;
                const int b1i = row1 >> 11, t1 = row1 & 2047;
                const size_t q1 = (((size_t)b1i * Hc + h) * Tc + t1) << 6;
                if (mat == 0) {
                    *(float2*)(Yq + q0 + d0) = v0;
                    *(float2*)(Yq + q1 + d0) = v1;
                } else {
                    const int dp0 = perm16(d0);
                    __nv_bfloat162 hh, ll;
                    split_bf16(v0.x, hh.x, ll.x);
                    split_bf16(v0.y, hh.y, ll.y);
                    *(__nv_bfloat162*)(Ykh + q0 + dp0) = hh;
                    *(__nv_bfloat162*)(Ykl + q0 + dp0) = ll;
                    split_bf16(v1.x, hh.x, ll.x);
                    split_bf16(v1.y, hh.y, ll.y);
                    *(__nv_bfloat162*)(Ykh + q1 + dp0) = hh;
                    *(__nv_bfloat162*)(Ykl + q1 + dp0) = ll;
                }
            }
        }
    }
}

// ---------------------------------------------------------------------------
// split-bf16 flash attention (R10/R13-proven), causal. AQ=64, AKT=64,
// 4 warps, P in registers, K+V double-buffered, occ 2.
// ---------------------------------------------------------------------------
constexpr int AQ  = 64;
constexpr int AKT = 64;
constexpr int RSK = 80;
constexpr int RSV = 80;
constexpr int KT_E = AKT * RSK;          // 5120
constexpr int VT_E = HDc * RSV;          // 5120
constexpr int ASTG_E = 2 * KT_E + 2 * VT_E;  // 20480 elements
constexpr int ATTN_SMEM = 2 * ASTG_E * 2;    // 81920 B

__global__ __launch_bounds__(128, 2)
void attn_bf16(const float* __restrict__ Q,
               const __nv_bfloat16* __restrict__ Khi, const __nv_bfloat16* __restrict__ Klo,
               const __nv_bfloat16* __restrict__ Vthi, const __nv_bfloat16* __restrict__ Vtlo,
               __nv_bfloat16* __restrict__ Ohi, __nv_bfloat16* __restrict__ Olo)
{
    extern __shared__ __align__(16) char asmem[];
    __nv_bfloat16* smem_bf = (__nv_bfloat16*)asmem;
    const uint32_t sb = smem_to_u32(asmem);
    const int tid = threadIdx.x, wid = tid >> 5, lane = tid & 31;
    const int g = lane >> 2, tg = lane & 3;
    const int bh = blockIdx.y;
    const int q0 = (int)(gridDim.x - 1 - blockIdx.x) * AQ;
    const int b = bh >> 4, h = bh & 15;
    const int nt = q0 / AKT + 1;

    uint32_t qhi[4][4], qlo[4][4];
    {
        const float* qb = Q + ((size_t)bh * Tc + q0 + wid * 16) * HDc;
        #pragma unroll
        for (int kk = 0; kk < 4; kk++) {
            const int ks = kk * 16 + 2 * tg;
            const float2 v00 = *(const float2*)&qb[(size_t)g * HDc + ks];
            const float2 v01 = *(const float2*)&qb[(size_t)g * HDc + ks + 8];
            const float2 v10 = *(const float2*)&qb[(size_t)(g + 8) * HDc + ks];
            const float2 v11 = *(const float2*)&qb[(size_t)(g + 8) * HDc + ks + 8];
            __nv_bfloat16 hx, lx, hy, ly;
            split_bf16(v00.x * 0.125f, hx, lx); split_bf16(v00.y * 0.125f, hy, ly);
            qhi[kk][0] = pack2(hx, hy); qlo[kk][0] = pack2(lx, ly);
            split_bf16(v10.x * 0.125f, hx, lx); split_bf16(v10.y * 0.125f, hy, ly);
            qhi[kk][1] = pack2(hx, hy); qlo[kk][1] = pack2(lx, ly);
            split_bf16(v01.x * 0.125f, hx, lx); split_bf16(v01.y * 0.125f, hy, ly);
            qhi[kk][2] = pack2(hx, hy); qlo[kk][2] = pack2(lx, ly);
            split_bf16(v11.x * 0.125f, hx, lx); split_bf16(v11.y * 0.125f, hy, ly);
            qhi[kk][3] = pack2(hx, hy); qlo[kk][3] = pack2(lx, ly);
        }
    }

    auto load_stage = [&](int t_, int s_) {
        const uint32_t base = sb + (uint32_t)(s_ * ASTG_E) * 2;
        const int k0_ = t_ * AKT;
        const size_t kg = ((size_t)bh * Tc + k0_) * HDc;
        const size_t vg = (size_t)bh * HDc * Tc + k0_;
        #pragma unroll
        for (int i = 0; i < 4; i++) {
            const int u = i * 128 + tid;
            const int r = u >> 3, c = u & 7;
            cp_async16(base + (uint32_t)(r * RSK + c * 8) * 2, Khi + kg + (size_t)r * HDc + c * 8);
        }
        #pragma unroll
        for (int i = 0; i < 4; i++) {
            const int u = i * 128 + tid;
            const int r = u >> 3, c = u & 7;
            cp_async16(base + (uint32_t)(KT_E + r * RSK + c * 8) * 2, Klo + kg + (size_t)r * HDc + c * 8);
        }
        #pragma unroll
        for (int i = 0; i < 4; i++) {
            const int u = i * 128 + tid;
            const int r = u >> 3, c = u & 7;
            cp_async16(base + (uint32_t)(2 * KT_E + r * RSV + c * 8) * 2,
                       Vthi + vg + (size_t)r * Tc + c * 8);
        }
        #pragma unroll
        for (int i = 0; i < 4; i++) {
            const int u = i * 128 + tid;
            const int r = u >> 3, c = u & 7;
            cp_async16(base + (uint32_t)(2 * KT_E + VT_E + r * RSV + c * 8) * 2,
                       Vtlo + vg + (size_t)r * Tc + c * 8);
        }
        cp_commit();
    };

    float acc_o[8][4] = {};
    float m0 = -INFINITY, m1 = -INFINITY, l0 = 0.f, l1 = 0.f;
    const int row0 = q0 + wid * 16 + g;

    load_stage(0, 0);
    if (nt > 1) load_stage(1, 1); else cp_commit();

    for (int t = 0; t < nt; t++) {
        const int s = t & 1;
        const int k0 = t * AKT;
        cp_wait<1>();
        __syncthreads();

        const __nv_bfloat16* Ks_hi = smem_bf + s * ASTG_E;
        const __nv_bfloat16* Ks_lo = Ks_hi + KT_E;
        const __nv_bfloat16* Vs_hi = Ks_hi + 2 * KT_E;
        const __nv_bfloat16* Vs_lo = Vs_hi + VT_E;

        float sacc[8][4] = {};
        #pragma unroll
        for (int kk = 0; kk < 4; kk++) {
            #pragma unroll
            for (int n_ = 0; n_ < 8; n_++) {
                const int r = (n_ * 8 + g) * RSK + kk * 16 + 4 * tg;
                const uint2 kh2 = *(const uint2*)(Ks_hi + r);
                const uint2 kl2 = *(const uint2*)(Ks_lo + r);
                uint32_t kh[2] = {kh2.x, kh2.y};
                uint32_t kl[2] = {kl2.x, kl2.y};
                mma_bf16(sacc[n_], qlo[kk], kh);
                mma_bf16(sacc[n_], qhi[kk], kl);
                mma_bf16(sacc[n_], qhi[kk], kh);
            }
        }

        if (k0 + AKT - 1 > q0 + wid * 16) {
            #pragma unroll
            for (int n_ = 0; n_ < 8; n_++) {
                const int c0 = k0 + n_ * 8 + 2 * tg;
                if (c0 > row0)     sacc[n_][0] = -1e30f;
                if (c0 + 1 > row0) sacc[n_][1] = -1e30f;
                if (c0 > row0 + 8)     sacc[n_][2] = -1e30f;
                if (c0 + 1 > row0 + 8) sacc[n_][3] = -1e30f;
            }
        }

        float tx0 = sacc[0][0], tx1 = sacc[0][2];
        #pragma unroll
        for (int n_ = 0; n_ < 8; n_++) {
            tx0 = fmaxf(tx0, fmaxf(sacc[n_][0], sacc[n_][1]));
            tx1 = fmaxf(tx1, fmaxf(sacc[n_][2], sacc[n_][3]));
        }
        tx0 = fmaxf(tx0, __shfl_xor_sync(0xffffffffu, tx0, 1));
        tx0 = fmaxf(tx0, __shfl_xor_sync(0xffffffffu, tx0, 2));
        tx1 = fmaxf(tx1, __shfl_xor_sync(0xffffffffu, tx1, 1));
        tx1 = fmaxf(tx1, __shfl_xor_sync(0xffffffffu, tx1, 2));
        const float mn0 = fmaxf(m0, tx0), mn1 = fmaxf(m1, tx1);
        const float c0f = __expf(m0 - mn0), c1f = __expf(m1 - mn1);
        m0 = mn0; m1 = mn1;

        float rs0 = 0.f, rs1 = 0.f;
        #pragma unroll
        for (int n_ = 0; n_ < 8; n_++) {
            sacc[n_][0] = __expf(sacc[n_][0] - mn0);
            sacc[n_][1] = __expf(sacc[n_][1] - mn0);
            sacc[n_][2] = __expf(sacc[n_][2] - mn1);
            sacc[n_][3] = __expf(sacc[n_][3] - mn1);
            rs0 += sacc[n_][0] + sacc[n_][1];
            rs1 += sacc[n_][2] + sacc[n_][3];
        }
        rs0 += __shfl_xor_sync(0xffffffffu, rs0, 1);
        rs0 += __shfl_xor_sync(0xffffffffu, rs0, 2);
        rs1 += __shfl_xor_sync(0xffffffffu, rs1, 1);
        rs1 += __shfl_xor_sync(0xffffffffu, rs1, 2);
        l0 = l0 * c0f + rs0;
        l1 = l1 * c1f + rs1;

        #pragma unroll
        for (int d8 = 0; d8 < 8; d8++) {
            acc_o[d8][0] *= c0f; acc_o[d8][1] *= c0f;
            acc_o[d8][2] *= c1f; acc_o[d8][3] *= c1f;
        }

        #pragma unroll
        for (int kk = 0; kk < 4; kk++) {
            uint32_t pah[4], pal[4];
            __nv_bfloat16 h0, l0b, h1, l1b;
            split_bf16(sacc[2*kk][0], h0, l0b); split_bf16(sacc[2*kk][1], h1, l1b);
            pah[0] = pack2(h0, h1); pal[0] = pack2(l0b, l1b);
            split_bf16(sacc[2*kk][2], h0, l0b); split_bf16(sacc[2*kk][3], h1, l1b);
            pah[1] = pack2(h0, h1); pal[1] = pack2(l0b, l1b);
            split_bf16(sacc[2*kk+1][0], h0, l0b); split_bf16(sacc[2*kk+1][1], h1, l1b);
            pah[2] = pack2(h0, h1); pal[2] = pack2(l0b, l1b);
            split_bf16(sacc[2*kk+1][2], h0, l0b); split_bf16(sacc[2*kk+1][3], h1, l1b);
            pah[3] = pack2(h0, h1); pal[3] = pack2(l0b, l1b);
            #pragma unroll
            for (int d8 = 0; d8 < 8; d8++) {
                const int r = (d8 * 8 + g) * RSV + kk * 16 + 4 * tg;
                const uint2 vh2 = *(const uint2*)(Vs_hi + r);
                const uint2 vl2 = *(const uint2*)(Vs_lo + r);
                uint32_t vh[2] = {vh2.x, vh2.y};
                uint32_t vl[2] = {vl2.x, vl2.y};
                mma_bf16(acc_o[d8], pal, vh);
                mma_bf16(acc_o[d8], pah, vl);
                mma_bf16(acc_o[d8], pah, vh);
            }
        }

        __syncthreads();
        if (t + 2 < nt) load_stage(t + 2, s); else cp_commit();
    }

    const float il0 = 1.f / l0, il1 = 1.f / l1;
    const size_t ob0 = ((size_t)b * Tc + row0) * Dc + (size_t)h * HDc;
    const size_t ob1 = ob0 + (size_t)8 * Dc;
    #pragma unroll
    for (int d8 = 0; d8 < 8; d8++) {
        const int c = d8 * 8 + 2 * tg;
        const int cp0 = perm16(c);
        const float v0 = acc_o[d8][0] * il0, v1 = acc_o[d8][1] * il0;
        const float v2 = acc_o[d8][2] * il1, v3 = acc_o[d8][3] * il1;
        __nv_bfloat162 hh, ll;
        split_bf16(v0, hh.x, ll.x); split_bf16(v1, hh.y, ll.y);
        *(__nv_bfloat162*)(Ohi + ob0 + cp0) = hh;
        *(__nv_bfloat162*)(Olo + ob0 + cp0) = ll;
        split_bf16(v2, hh.x, ll.x); split_bf16(v3, hh.y, ll.y);
        *(__nv_bfloat162*)(Ohi + ob1 + cp0) = hh;
        *(__nv_bfloat162*)(Olo + ob1 + cp0) = ll;
    }
}

// ---------------------------------------------------------------------------
// Launch
// ---------------------------------------------------------------------------
extern "C" void kernel_launch(void* const* d_in, const int* in_sizes, int n_in,
                              void* d_out, int out_size)
{
    const float* x  = (const float*)d_in[0];
    const float* Wq = (const float*)d_in[1];
    const float* bq = (const float*)d_in[2];
    const float* Wk = (const float*)d_in[3];
    const float* bk = (const float*)d_in[4];
    const float* Wv = (const float*)d_in[5];
    const float* bv = (const float*)d_in[6];
    const float* Wo = (const float*)d_in[7];
    const float* bo = (const float*)d_in[8];
    float* out = (float*)d_out;

    __nv_bfloat16 *Xhi, *Xlo, *Khi, *Klo, *Vthi, *Vtlo, *Ahi, *Alo, *Whi, *Wlo;
    float *Qp;
    cudaGetSymbolAddress((void**)&Xhi, g_Xhi);
    cudaGetSymbolAddress((void**)&Xlo, g_Xlo);
    cudaGetSymbolAddress((void**)&Qp, g_Q);
    cudaGetSymbolAddress((void**)&Khi, g_Khi);
    cudaGetSymbolAddress((void**)&Klo, g_Klo);
    cudaGetSymbolAddress((void**)&Vthi, g_Vthi);
    cudaGetSymbolAddress((void**)&Vtlo, g_Vtlo);
    cudaGetSymbolAddress((void**)&Ahi, g_Ahi);
    cudaGetSymbolAddress((void**)&Alo, g_Alo);
    cudaGetSymbolAddress((void**)&Whi, g_Wthi);
    cudaGetSymbolAddress((void**)&Wlo, g_Wtlo);

    cudaFuncSetAttribute(gemm_bf16x3<false>, cudaFuncAttributeMaxDynamicSharedMemorySize, GEMM_SMEM);
    cudaFuncSetAttribute(gemm_bf16x3<true>,  cudaFuncAttributeMaxDynamicSharedMemorySize, GEMM_SMEM);
    cudaFuncSetAttribute(attn_bf16, cudaFuncAttributeMaxDynamicSharedMemorySize, ATTN_SMEM);

    // 1) prep: split+permute X; transpose+split+permute weights
    const int n2 = Mc * Dc / 2;
    split_permK_bf16<<<(n2 + 255) / 256, 256>>>(x, Xhi, Xlo, n2);
    transpose4_split<<<dim3(32, 32, 4), dim3(32, 8)>>>(Wq, Wk, Wv, Wo, Whi, Wlo);

    // 2) fused Q+K+V projection (one GEMM over N=3072; V written transposed+split)
    const dim3 gqkv(3 * Dc / BN, Mc / BM);   // (24, 32)
    gemm_bf16x3<true><<<gqkv, 256, GEMM_SMEM>>>(Xhi, Xlo, Whi, Wlo,
                                                bq, bk, bv, Qp, Khi, Klo, Vthi, Vtlo);

    // 3) attention (P-in-registers, AKT=64, occ 2)
    const dim3 ag(Tc / AQ, Bc * Hc);   // (32, 32)
    attn_bf16<<<ag, 128, ATTN_SMEM>>>(Qp, Khi, Klo, Vthi, Vtlo, Ahi, Alo);

    // 4) output projection -> d_out
    const dim3 go(Dc / BN, Mc / BM);   // (8, 32)
    const size_t DD = (size_t)Dc * Dc;
    gemm_bf16x3<false><<<go, 256, GEMM_SMEM>>>(Ahi, Alo, Whi + 3 * DD, Wlo + 3 * DD,
                                               bo, nullptr, nullptr, out, nullptr, nullptr,
                                               nullptr, nullptr);
}